// round 14
// baseline (speedup 1.0000x reference)
#include <cuda_runtime.h>
#include <cuda_bf16.h>
#include <cstdint>

constexpr int Bc = 4, Sc = 128, Hc = 32, Dc = 128, Tc = 2048;
constexpr int HD  = Hc * Dc;          // 4096
constexpr int KVB = 64;
constexpr int NT  = 512;              // threads

// smem layout (bytes)
constexpr uint32_t QHI  = 0;          // 128x128 bf16 = 32KB  (epilogue: lred at smc+0)
constexpr uint32_t QLO  = 32768;
constexpr uint32_t TIL  = 65536;      // 2 buffers x 64KB: [KHI|KLO|VHI|VLO] each 16KB
constexpr uint32_t TKHI = 0, TKLO = 16384, TVHI = 32768, TVLO = 49152;
constexpr uint32_t BUFS = 65536;
constexpr uint32_t STGK = 196608;     // K fp32 staging 32KB
constexpr uint32_t SMEM_BYTES = 229376;   // 224KB

__device__ __forceinline__ uint32_t swz_w(int r, int d0) {   // 8B store addr (256B rows)
    return (uint32_t)(r * 256 + ((((d0 >> 3)) ^ (r & 7)) << 4) + ((d0 & 7) << 1));
}
__device__ __forceinline__ uint32_t swz_l(int r, int c0) {   // ldmatrix row addr (256B rows)
    return (uint32_t)(r * 256 + ((((c0 >> 3)) ^ (r & 7)) << 4));
}
__device__ __forceinline__ uint32_t smem_u32(const void* p) {
    uint32_t r;
    asm("{\n\t.reg .u64 t;\n\tcvta.to.shared.u64 t, %1;\n\tcvt.u32.u64 %0, t;\n\t}"
        : "=r"(r) : "l"(p));
    return r;
}

#define LDSM4(R0,R1,R2,R3,A) \
    asm volatile("ldmatrix.sync.aligned.m8n8.x4.shared.b16 {%0,%1,%2,%3}, [%4];" \
        : "=r"(R0),"=r"(R1),"=r"(R2),"=r"(R3) : "r"(A))
#define LDSM4T(R0,R1,R2,R3,A) \
    asm volatile("ldmatrix.sync.aligned.m8n8.x4.trans.shared.b16 {%0,%1,%2,%3}, [%4];" \
        : "=r"(R0),"=r"(R1),"=r"(R2),"=r"(R3) : "r"(A))
#define MMA(C,A0,A1,A2,A3,B0,B1) \
    asm volatile("mma.sync.aligned.m16n8k16.row.col.f32.bf16.bf16.f32 " \
        "{%0,%1,%2,%3}, {%4,%5,%6,%7}, {%8,%9}, {%0,%1,%2,%3};" \
        : "+f"((C)[0]),"+f"((C)[1]),"+f"((C)[2]),"+f"((C)[3]) \
        : "r"(A0),"r"(A1),"r"(A2),"r"(A3),"r"(B0),"r"(B1))

__device__ __forceinline__ void cp16(uint32_t dst, const void* src) {
    asm volatile("cp.async.cg.shared.global [%0], [%1], 16;"
                 :: "r"(dst), "l"(src) : "memory");
}
__device__ __forceinline__ void cp_commit() { asm volatile("cp.async.commit_group;" ::: "memory"); }
__device__ __forceinline__ void cp_wait0()  { asm volatile("cp.async.wait_group 0;" ::: "memory"); }

__device__ __forceinline__ uint32_t pk_us(unsigned short a, unsigned short b) {
    return (uint32_t)a | ((uint32_t)b << 16);
}
__device__ __forceinline__ void split2(float2 v, uint32_t& hi, uint32_t& lo) {
    __nv_bfloat16 h0 = __float2bfloat16(v.x), h1 = __float2bfloat16(v.y);
    hi = pk_us(__bfloat16_as_ushort(h0), __bfloat16_as_ushort(h1));
    lo = pk_us(__bfloat16_as_ushort(__float2bfloat16(v.x - __bfloat162float(h0))),
               __bfloat16_as_ushort(__float2bfloat16(v.y - __bfloat162float(h1))));
}
__device__ __forceinline__ void split4(float4 v, uint2& hi, uint2& lo) {
    uint32_t h0, l0, h1, l1;
    split2(make_float2(v.x, v.y), h0, l0);
    split2(make_float2(v.z, v.w), h1, l1);
    hi = make_uint2(h0, h1); lo = make_uint2(l0, l1);
}

__global__ void __launch_bounds__(NT, 1)
sdpa_hmma9_kernel(const float* __restrict__ gq, const float* __restrict__ gk,
                  const float* __restrict__ gv, const float* __restrict__ gkc,
                  const float* __restrict__ gvc, const int* __restrict__ gpos,
                  float* __restrict__ gout)
{
    extern __shared__ char smc[];
    const uint32_t sb = smem_u32(smc);
    const int tid = threadIdx.x;
    const int wid = tid >> 5;
    const int l   = tid & 31;
    const int qt  = wid & 7;          // query tile (16 rows)
    const int s   = wid >> 3;         // key half (32 keys)
    const int bh = blockIdx.x, b = bh >> 5, h = bh & 31;

    const int start = *gpos;
    const int nkv   = start + Sc;
    const int nblk  = (nkv + KVB - 1) / KVB;

    const float* qb  = gq  + ((size_t)(b * Sc) * Hc + h) * Dc;
    const float* kcb = gkc + ((size_t)(b * Tc) * Hc + h) * Dc;
    const float* vcb = gvc + ((size_t)(b * Tc) * Hc + h) * Dc;
    const float* knb = gk  + ((size_t)(b * Sc) * Hc + h) * Dc;
    const float* vnb = gv  + ((size_t)(b * Sc) * Hc + h) * Dc;

    // per-thread staging coords
    const int skey = tid >> 5;                 // 0..15 (4 iters add +16 each... below)
    // (loops use idx = tid + it*NT)

    // ---- stage K block 0 via cp.async ----
    #pragma unroll
    for (int it = 0; it < 4; it++) {
        int idx = tid + it * NT;
        int key = idx >> 5, d = (idx & 31) * 4;
        const float* ks = (key < start) ? kcb + (size_t)key * HD + d
                                        : knb + (size_t)(key - start) * HD + d;
        cp16(sb + STGK + (uint32_t)idx * 16, ks);
    }
    cp_commit();

    // ---- prologue: Q -> smem hi/lo, scale*log2(e) folded ----
    const float SCALE = 0.08838834764831845f * 1.4426950408889634f;
    #pragma unroll
    for (int it = 0; it < 8; it++) {
        int idx = tid + it * NT;
        int r = idx >> 5, d = (idx & 31) * 4;
        float4 qv = *(const float4*)(qb + (size_t)r * HD + d);
        qv.x *= SCALE; qv.y *= SCALE; qv.z *= SCALE; qv.w *= SCALE;
        uint2 hi, lo; split4(qv, hi, lo);
        uint32_t o = swz_w(r, d);
        *(uint2*)(smc + QHI + o) = hi;
        *(uint2*)(smc + QLO + o) = lo;
    }

    // ---- V block 0 via LDG -> convert -> buf0 ----
    {
        #pragma unroll
        for (int it = 0; it < 4; it++) {
            int idx = tid + it * NT;
            int key = idx >> 5, d = (idx & 31) * 4;
            float4 vv = (key < start) ? *(const float4*)(vcb + (size_t)key * HD + d)
                                      : *(const float4*)(vnb + (size_t)(key - start) * HD + d);
            uint2 hi, lo; split4(vv, hi, lo);
            uint32_t o = swz_w(key, d);
            *(uint2*)(smc + TIL + TVHI + o) = hi;
            *(uint2*)(smc + TIL + TVLO + o) = lo;
        }
    }
    // ---- K block 0 convert -> buf0 ----
    cp_wait0();
    #pragma unroll
    for (int it = 0; it < 4; it++) {
        int idx = tid + it * NT;
        int key = idx >> 5, d = (idx & 31) * 4;
        uint32_t o = swz_w(key, d);
        uint2 hi, lo;
        split4(*(const float4*)(smc + STGK + (size_t)idx * 16), hi, lo);
        *(uint2*)(smc + TIL + TKHI + o) = hi; *(uint2*)(smc + TIL + TKLO + o) = lo;
    }

    float O[16][4];
    #pragma unroll
    for (int t = 0; t < 16; t++) { O[t][0]=O[t][1]=O[t][2]=O[t][3]=0.f; }
    float lacc0 = 0.f, lacc1 = 0.f;

    // fragment address constants
    const int q0   = qt * 16;
    const int row0 = q0 + (l >> 2);
    const int qrow = q0 + (l & 15);
    const int qc8  = (l >> 4) << 3;
    const int krow = (l & 7) + ((l >> 4) << 3);
    const int kc8  = ((l >> 3) & 1) << 3;
    const int vrow = (l & 7) + (((l >> 3) & 1) << 3);
    const int vc8  = (l >> 4) << 3;
    const int colb = (l & 3) * 2;

    __syncthreads();   // publish Q + buf0 tiles

    for (int blk = 0; blk < nblk; blk++) {
        const int t0 = blk * KVB;
        const bool pf = (blk + 1) < nblk;
        const uint32_t cur = TIL + (uint32_t)(blk & 1) * BUFS;
        const uint32_t nxt = TIL + (uint32_t)((blk + 1) & 1) * BUFS;

        // ---- cp.async K(next) into staging (background) ----
        if (pf) {
            const int t0n = t0 + KVB;
            #pragma unroll
            for (int it = 0; it < 4; it++) {
                int idx = tid + it * NT;
                int key = idx >> 5, d = (idx & 31) * 4;
                int jg  = t0n + key;
                const float* ks = (jg < start) ? kcb + (size_t)jg * HD + d
                                               : knb + (size_t)(jg - start) * HD + d;
                cp16(sb + STGK + (uint32_t)idx * 16, ks);
            }
            cp_commit();
        }

        // ---- QK^T: this warp's 32-key half ----
        float S[4][4];
        #pragma unroll
        for (int t = 0; t < 4; t++) { S[t][0]=S[t][1]=S[t][2]=S[t][3]=0.f; }

        #pragma unroll
        for (int ks = 0; ks < 8; ks++) {
            int c0k = ks * 16 + kc8;
            uint32_t qh0,qh1,qh2,qh3, ql0,ql1,ql2,ql3;
            uint32_t qo = swz_l(qrow, ks * 16 + qc8);
            LDSM4(qh0,qh1,qh2,qh3, sb + QHI + qo);
            uint32_t khf[2][4];
            #pragma unroll
            for (int np = 0; np < 2; np++) {
                uint32_t ko = swz_l(s * 32 + np * 16 + krow, c0k);
                LDSM4(khf[np][0],khf[np][1],khf[np][2],khf[np][3], sb + cur + TKHI + ko);
            }
            #pragma unroll
            for (int np = 0; np < 2; np++) {   // hi x hi
                MMA(S[2*np  ], qh0,qh1,qh2,qh3, khf[np][0],khf[np][1]);
                MMA(S[2*np+1], qh0,qh1,qh2,qh3, khf[np][2],khf[np][3]);
            }
            LDSM4(ql0,ql1,ql2,ql3, sb + QLO + qo);
            #pragma unroll
            for (int np = 0; np < 2; np++) {   // lo x hi
                MMA(S[2*np  ], ql0,ql1,ql2,ql3, khf[np][0],khf[np][1]);
                MMA(S[2*np+1], ql0,ql1,ql2,ql3, khf[np][2],khf[np][3]);
            }
            uint32_t klf[2][4];
            #pragma unroll
            for (int np = 0; np < 2; np++) {
                uint32_t ko = swz_l(s * 32 + np * 16 + krow, c0k);
                LDSM4(klf[np][0],klf[np][1],klf[np][2],klf[np][3], sb + cur + TKLO + ko);
            }
            #pragma unroll
            for (int np = 0; np < 2; np++) {   // hi x lo
                MMA(S[2*np  ], qh0,qh1,qh2,qh3, klf[np][0],klf[np][1]);
                MMA(S[2*np+1], qh0,qh1,qh2,qh3, klf[np][2],klf[np][3]);
            }
        }

        // ---- convert K(next) staging -> nxt tiles; then LDG V(next) ----
        if (pf) {
            cp_wait0();
            #pragma unroll
            for (int it = 0; it < 4; it++) {
                int idx = tid + it * NT;
                int key = idx >> 5, d = (idx & 31) * 4;
                uint32_t o = swz_w(key, d);
                uint2 hi, lo;
                split4(*(const float4*)(smc + STGK + (size_t)idx * 16), hi, lo);
                *(uint2*)(smc + nxt + TKHI + o) = hi; *(uint2*)(smc + nxt + TKLO + o) = lo;
            }
        }
        float4 vreg[4];
        if (pf) {
            const int t0n = t0 + KVB;
            #pragma unroll
            for (int it = 0; it < 4; it++) {
                int idx = tid + it * NT;
                int key = idx >> 5, d = (idx & 31) * 4;
                int jg  = t0n + key;
                vreg[it] = (jg < start) ? *(const float4*)(vcb + (size_t)jg * HD + d)
                                        : *(const float4*)(vnb + (size_t)(jg - start) * HD + d);
            }
        }

        // ---- softmax + P repack to registers (A-fragments) ----
        uint32_t ph[2][4], pl[2][4];
        const bool needMask = (t0 + s * 32 + 31 - start) > q0;
        #pragma unroll
        for (int nt = 0; nt < 4; nt++) {
            float p0, p1, p2, p3;
            if (!needMask) {
                p0 = exp2f(S[nt][0]); p1 = exp2f(S[nt][1]);
                p2 = exp2f(S[nt][2]); p3 = exp2f(S[nt][3]);
            } else {
                int j0 = t0 + s * 32 + nt * 8 + colb - start;
                p0 = (j0     > row0    ) ? 0.f : exp2f(S[nt][0]);
                p1 = (j0 + 1 > row0    ) ? 0.f : exp2f(S[nt][1]);
                p2 = (j0     > row0 + 8) ? 0.f : exp2f(S[nt][2]);
                p3 = (j0 + 1 > row0 + 8) ? 0.f : exp2f(S[nt][3]);
            }
            lacc0 += p0 + p1;  lacc1 += p2 + p3;
            __nv_bfloat16 b0 = __float2bfloat16(p0), b1 = __float2bfloat16(p1);
            __nv_bfloat16 b2 = __float2bfloat16(p2), b3 = __float2bfloat16(p3);
            int kg = nt >> 1, sl = (nt & 1) * 2;
            ph[kg][sl  ] = pk_us(__bfloat16_as_ushort(b0), __bfloat16_as_ushort(b1));
            ph[kg][sl+1] = pk_us(__bfloat16_as_ushort(b2), __bfloat16_as_ushort(b3));
            pl[kg][sl  ] = pk_us(
                __bfloat16_as_ushort(__float2bfloat16(p0 - __bfloat162float(b0))),
                __bfloat16_as_ushort(__float2bfloat16(p1 - __bfloat162float(b1))));
            pl[kg][sl+1] = pk_us(
                __bfloat16_as_ushort(__float2bfloat16(p2 - __bfloat162float(b2))),
                __bfloat16_as_ushort(__float2bfloat16(p3 - __bfloat162float(b3))));
        }

        // ---- PV: this warp's 32 keys x ALL 128 d, partial O ----
        #pragma unroll
        for (int kg = 0; kg < 2; kg++) {
            int vr = s * 32 + kg * 16 + vrow;
            #pragma unroll
            for (int dq = 0; dq < 4; dq++) {
                uint32_t vh[2][4], vl[2][4];
                #pragma unroll
                for (int u = 0; u < 2; u++) {
                    uint32_t vo = swz_l(vr, (dq * 2 + u) * 16 + vc8);
                    LDSM4T(vh[u][0],vh[u][1],vh[u][2],vh[u][3], sb + cur + TVHI + vo);
                    LDSM4T(vl[u][0],vl[u][1],vl[u][2],vl[u][3], sb + cur + TVLO + vo);
                }
                #pragma unroll
                for (int u = 0; u < 2; u++) {
                    MMA(O[2*(dq*2+u)  ], ph[kg][0],ph[kg][1],ph[kg][2],ph[kg][3], vh[u][0],vh[u][1]);
                    MMA(O[2*(dq*2+u)+1], ph[kg][0],ph[kg][1],ph[kg][2],ph[kg][3], vh[u][2],vh[u][3]);
                }
                #pragma unroll
                for (int u = 0; u < 2; u++) {
                    MMA(O[2*(dq*2+u)  ], ph[kg][0],ph[kg][1],ph[kg][2],ph[kg][3], vl[u][0],vl[u][1]);
                    MMA(O[2*(dq*2+u)+1], ph[kg][0],ph[kg][1],ph[kg][2],ph[kg][3], vl[u][2],vl[u][3]);
                }
                #pragma unroll
                for (int u = 0; u < 2; u++) {
                    MMA(O[2*(dq*2+u)  ], pl[kg][0],pl[kg][1],pl[kg][2],pl[kg][3], vh[u][0],vh[u][1]);
                    MMA(O[2*(dq*2+u)+1], pl[kg][0],pl[kg][1],pl[kg][2],pl[kg][3], vh[u][2],vh[u][3]);
                }
            }
        }

        // ---- convert V(next) regs -> nxt tiles; ONE barrier per block ----
        if (pf) {
            #pragma unroll
            for (int it = 0; it < 4; it++) {
                int idx = tid + it * NT;
                int key = idx >> 5, d = (idx & 31) * 4;
                uint32_t o = swz_w(key, d);
                uint2 hi, lo; split4(vreg[it], hi, lo);
                *(uint2*)(smc + nxt + TVHI + o) = hi;
                *(uint2*)(smc + nxt + TVLO + o) = lo;
            }
            __syncthreads();   // publish nxt tiles; all reads of cur complete
        }
    }

    // ---- epilogue: reduce l (quad), combine O + l across s halves ----
    lacc0 += __shfl_xor_sync(0xffffffffu, lacc0, 1);
    lacc0 += __shfl_xor_sync(0xffffffffu, lacc0, 2);
    lacc1 += __shfl_xor_sync(0xffffffffu, lacc1, 1);
    lacc1 += __shfl_xor_sync(0xffffffffu, lacc1, 2);

    float* ored = (float*)(smc + TIL);    // tile region dead: [128][128] fp32 = 64KB
    float* lred = (float*)smc;            // Q region dead: 512B for l sums
    __syncthreads();                      // all warps past mainloop

    if (s == 1) {
        if ((l & 3) == 0) { lred[row0] = lacc0; lred[row0 + 8] = lacc1; }
        #pragma unroll
        for (int nt = 0; nt < 16; nt++) {
            int d = nt * 8 + colb;
            *(float2*)(ored + (size_t)row0 * 128 + d)       = make_float2(O[nt][0], O[nt][1]);
            *(float2*)(ored + (size_t)(row0 + 8) * 128 + d) = make_float2(O[nt][2], O[nt][3]);
        }
    }
    __syncthreads();
    if (s == 0) {
        const float inv0 = 1.f / (lacc0 + lred[row0]);
        const float inv1 = 1.f / (lacc1 + lred[row0 + 8]);
        float* o0 = gout + ((size_t)(b * Sc + row0    ) * HD) + h * Dc;
        float* o1 = gout + ((size_t)(b * Sc + row0 + 8) * HD) + h * Dc;
        #pragma unroll
        for (int nt = 0; nt < 16; nt++) {
            int d = nt * 8 + colb;
            float2 a0 = *(const float2*)(ored + (size_t)row0 * 128 + d);
            float2 a1 = *(const float2*)(ored + (size_t)(row0 + 8) * 128 + d);
            *(float2*)(o0 + d) = make_float2((O[nt][0] + a0.x) * inv0, (O[nt][1] + a0.y) * inv0);
            *(float2*)(o1 + d) = make_float2((O[nt][2] + a1.x) * inv1, (O[nt][3] + a1.y) * inv1);
        }
    }
}

extern "C" void kernel_launch(void* const* d_in, const int* in_sizes, int n_in,
                              void* d_out, int out_size)
{
    const float* q  = (const float*)d_in[0];
    const float* k  = (const float*)d_in[1];
    const float* v  = (const float*)d_in[2];
    const float* kc = (const float*)d_in[3];
    const float* vc = (const float*)d_in[4];
    const int*  pos = (const int*)d_in[5];
    float* out = (float*)d_out;

    cudaFuncSetAttribute(sdpa_hmma9_kernel,
                         cudaFuncAttributeMaxDynamicSharedMemorySize, SMEM_BYTES);
    sdpa_hmma9_kernel<<<Bc * Hc, NT, SMEM_BYTES>>>(q, k, v, kc, vc, pos, out);
}

// round 15
// speedup vs baseline: 1.3874x; 1.3874x over previous
#include <cuda_runtime.h>
#include <cuda_fp16.h>
#include <cstdint>

constexpr int Bc = 4, Sc = 128, Hc = 32, Dc = 128, Tc = 2048;
constexpr int HD  = Hc * Dc;          // 4096
constexpr int KVB = 64;
constexpr int NT  = 512;              // threads

// smem layout (bytes)
constexpr uint32_t QHI  = 0;          // 128x128 fp16 = 32KB (epilogue: lred at smc+0)
constexpr uint32_t QLO  = 32768;
constexpr uint32_t KTI  = 65536;      // 64x128 fp16 = 16KB (single precision)
constexpr uint32_t VTI  = 81920;      // 16KB
constexpr uint32_t STGK = 98304;      // 64x128 fp32 = 32KB (epilogue: ored 64KB = STGK+STGV)
constexpr uint32_t STGV = 131072;
constexpr uint32_t SMEM_BYTES = 163840;   // 160KB

__device__ __forceinline__ uint32_t swz_w(int r, int d0) {   // 8B store addr (256B rows)
    return (uint32_t)(r * 256 + ((((d0 >> 3)) ^ (r & 7)) << 4) + ((d0 & 7) << 1));
}
__device__ __forceinline__ uint32_t swz_l(int r, int c0) {   // ldmatrix row addr (256B rows)
    return (uint32_t)(r * 256 + ((((c0 >> 3)) ^ (r & 7)) << 4));
}
__device__ __forceinline__ uint32_t smem_u32(const void* p) {
    uint32_t r;
    asm("{\n\t.reg .u64 t;\n\tcvta.to.shared.u64 t, %1;\n\tcvt.u32.u64 %0, t;\n\t}"
        : "=r"(r) : "l"(p));
    return r;
}

#define LDSM4(R0,R1,R2,R3,A) \
    asm volatile("ldmatrix.sync.aligned.m8n8.x4.shared.b16 {%0,%1,%2,%3}, [%4];" \
        : "=r"(R0),"=r"(R1),"=r"(R2),"=r"(R3) : "r"(A))
#define LDSM4T(R0,R1,R2,R3,A) \
    asm volatile("ldmatrix.sync.aligned.m8n8.x4.trans.shared.b16 {%0,%1,%2,%3}, [%4];" \
        : "=r"(R0),"=r"(R1),"=r"(R2),"=r"(R3) : "r"(A))
#define MMA(C,A0,A1,A2,A3,B0,B1) \
    asm volatile("mma.sync.aligned.m16n8k16.row.col.f32.f16.f16.f32 " \
        "{%0,%1,%2,%3}, {%4,%5,%6,%7}, {%8,%9}, {%0,%1,%2,%3};" \
        : "+f"((C)[0]),"+f"((C)[1]),"+f"((C)[2]),"+f"((C)[3]) \
        : "r"(A0),"r"(A1),"r"(A2),"r"(A3),"r"(B0),"r"(B1))

__device__ __forceinline__ void cp16(uint32_t dst, const void* src) {
    asm volatile("cp.async.cg.shared.global [%0], [%1], 16;"
                 :: "r"(dst), "l"(src) : "memory");
}
__device__ __forceinline__ void cp_commit() { asm volatile("cp.async.commit_group;" ::: "memory"); }
__device__ __forceinline__ void cp_wait0()  { asm volatile("cp.async.wait_group 0;" ::: "memory"); }

__device__ __forceinline__ uint32_t pk_us(unsigned short a, unsigned short b) {
    return (uint32_t)a | ((uint32_t)b << 16);
}
// split fp32 pair -> fp16 hi + fp16 lo residual (packed)
__device__ __forceinline__ void split2h(float2 v, uint32_t& hi, uint32_t& lo) {
    __half h0 = __float2half_rn(v.x), h1 = __float2half_rn(v.y);
    hi = pk_us(__half_as_ushort(h0), __half_as_ushort(h1));
    lo = pk_us(__half_as_ushort(__float2half_rn(v.x - __half2float(h0))),
               __half_as_ushort(__float2half_rn(v.y - __half2float(h1))));
}
__device__ __forceinline__ void split4h(float4 v, uint2& hi, uint2& lo) {
    uint32_t h0, l0, h1, l1;
    split2h(make_float2(v.x, v.y), h0, l0);
    split2h(make_float2(v.z, v.w), h1, l1);
    hi = make_uint2(h0, h1); lo = make_uint2(l0, l1);
}
// single-precision fp16 convert (for K, V)
__device__ __forceinline__ uint2 cvt4h(float4 v) {
    return make_uint2(
        pk_us(__half_as_ushort(__float2half_rn(v.x)), __half_as_ushort(__float2half_rn(v.y))),
        pk_us(__half_as_ushort(__float2half_rn(v.z)), __half_as_ushort(__float2half_rn(v.w))));
}

__global__ void __launch_bounds__(NT, 1)
sdpa_h16_kernel(const float* __restrict__ gq, const float* __restrict__ gk,
                const float* __restrict__ gv, const float* __restrict__ gkc,
                const float* __restrict__ gvc, const int* __restrict__ gpos,
                float* __restrict__ gout)
{
    extern __shared__ char smc[];
    const uint32_t sb = smem_u32(smc);
    const int tid = threadIdx.x;
    const int wid = tid >> 5;
    const int l   = tid & 31;
    const int qt  = wid & 7;          // query tile (16 rows)
    const int s   = wid >> 3;         // key half (32 keys)
    const int bh = blockIdx.x, b = bh >> 5, h = bh & 31;

    const int start = *gpos;
    const int nkv   = start + Sc;
    const int nblk  = (nkv + KVB - 1) / KVB;

    const float* qb  = gq  + ((size_t)(b * Sc) * Hc + h) * Dc;
    const float* kcb = gkc + ((size_t)(b * Tc) * Hc + h) * Dc;
    const float* vcb = gvc + ((size_t)(b * Tc) * Hc + h) * Dc;
    const float* knb = gk  + ((size_t)(b * Sc) * Hc + h) * Dc;
    const float* vnb = gv  + ((size_t)(b * Sc) * Hc + h) * Dc;

    // ---- stage block 0 (K + V fp32) ----
    #pragma unroll
    for (int it = 0; it < 4; it++) {
        int idx = tid + it * NT;
        int key = idx >> 5, d = (idx & 31) * 4;
        const float* ks = (key < start) ? kcb + (size_t)key * HD + d
                                        : knb + (size_t)(key - start) * HD + d;
        const float* vs = (key < start) ? vcb + (size_t)key * HD + d
                                        : vnb + (size_t)(key - start) * HD + d;
        cp16(sb + STGK + (uint32_t)idx * 16, ks);
        cp16(sb + STGV + (uint32_t)idx * 16, vs);
    }
    cp_commit();

    // ---- prologue: Q -> smem fp16 hi/lo, scale*log2(e) folded ----
    const float SCALE = 0.08838834764831845f * 1.4426950408889634f;
    #pragma unroll
    for (int it = 0; it < 8; it++) {
        int idx = tid + it * NT;
        int r = idx >> 5, d = (idx & 31) * 4;
        float4 qv = *(const float4*)(qb + (size_t)r * HD + d);
        qv.x *= SCALE; qv.y *= SCALE; qv.z *= SCALE; qv.w *= SCALE;
        uint2 hi, lo; split4h(qv, hi, lo);
        uint32_t o = swz_w(r, d);
        *(uint2*)(smc + QHI + o) = hi;
        *(uint2*)(smc + QLO + o) = lo;
    }

    float O[16][4];
    #pragma unroll
    for (int t = 0; t < 16; t++) { O[t][0]=O[t][1]=O[t][2]=O[t][3]=0.f; }
    float lacc0 = 0.f, lacc1 = 0.f;

    // fragment address constants
    const int q0   = qt * 16;
    const int row0 = q0 + (l >> 2);
    const int qrow = q0 + (l & 15);
    const int qc8  = (l >> 4) << 3;
    const int krow = (l & 7) + ((l >> 4) << 3);
    const int kc8  = ((l >> 3) & 1) << 3;
    const int vrow = (l & 7) + (((l >> 3) & 1) << 3);
    const int vc8  = (l >> 4) << 3;
    const int colb = (l & 3) * 2;

    // ---- convert block 0 staging -> single-fp16 tiles ----
    cp_wait0();
    #pragma unroll
    for (int it = 0; it < 4; it++) {
        int idx = tid + it * NT;
        int key = idx >> 5, d = (idx & 31) * 4;
        uint32_t o = swz_w(key, d);
        *(uint2*)(smc + KTI + o) = cvt4h(*(const float4*)(smc + STGK + (size_t)idx * 16));
        *(uint2*)(smc + VTI + o) = cvt4h(*(const float4*)(smc + STGV + (size_t)idx * 16));
    }
    __syncthreads();   // publish Q + tiles

    for (int blk = 0; blk < nblk; blk++) {
        const int t0 = blk * KVB;
        const bool pf = (blk + 1) < nblk;

        // ---- cp.async next block into staging (background) ----
        if (pf) {
            const int t0n = t0 + KVB;
            #pragma unroll
            for (int it = 0; it < 4; it++) {
                int idx = tid + it * NT;
                int key = idx >> 5, d = (idx & 31) * 4;
                int jg  = t0n + key;
                const float* ks = (jg < start) ? kcb + (size_t)jg * HD + d
                                               : knb + (size_t)(jg - start) * HD + d;
                const float* vs = (jg < start) ? vcb + (size_t)jg * HD + d
                                               : vnb + (size_t)(jg - start) * HD + d;
                cp16(sb + STGK + (uint32_t)idx * 16, ks);
                cp16(sb + STGV + (uint32_t)idx * 16, vs);
            }
            cp_commit();
        }

        // ---- QK^T: this warp's 32-key half; 2 terms (Qhi,Qlo) x K ----
        float S[4][4];
        #pragma unroll
        for (int t = 0; t < 4; t++) { S[t][0]=S[t][1]=S[t][2]=S[t][3]=0.f; }

        #pragma unroll
        for (int ks = 0; ks < 8; ks++) {
            int c0k = ks * 16 + kc8;
            uint32_t qh0,qh1,qh2,qh3, ql0,ql1,ql2,ql3;
            uint32_t qo = swz_l(qrow, ks * 16 + qc8);
            LDSM4(qh0,qh1,qh2,qh3, sb + QHI + qo);
            uint32_t khf[2][4];
            #pragma unroll
            for (int np = 0; np < 2; np++) {
                uint32_t ko = swz_l(s * 32 + np * 16 + krow, c0k);
                LDSM4(khf[np][0],khf[np][1],khf[np][2],khf[np][3], sb + KTI + ko);
            }
            #pragma unroll
            for (int np = 0; np < 2; np++) {   // Qhi x K
                MMA(S[2*np  ], qh0,qh1,qh2,qh3, khf[np][0],khf[np][1]);
                MMA(S[2*np+1], qh0,qh1,qh2,qh3, khf[np][2],khf[np][3]);
            }
            LDSM4(ql0,ql1,ql2,ql3, sb + QLO + qo);
            #pragma unroll
            for (int np = 0; np < 2; np++) {   // Qlo x K
                MMA(S[2*np  ], ql0,ql1,ql2,ql3, khf[np][0],khf[np][1]);
                MMA(S[2*np+1], ql0,ql1,ql2,ql3, khf[np][2],khf[np][3]);
            }
        }

        // ---- softmax + P repack to fp16 hi/lo A-fragments ----
        uint32_t ph[2][4], pl[2][4];
        const bool needMask = (t0 + s * 32 + 31 - start) > q0;
        #pragma unroll
        for (int nt = 0; nt < 4; nt++) {
            float p0, p1, p2, p3;
            if (!needMask) {
                p0 = exp2f(S[nt][0]); p1 = exp2f(S[nt][1]);
                p2 = exp2f(S[nt][2]); p3 = exp2f(S[nt][3]);
            } else {
                int j0 = t0 + s * 32 + nt * 8 + colb - start;
                p0 = (j0     > row0    ) ? 0.f : exp2f(S[nt][0]);
                p1 = (j0 + 1 > row0    ) ? 0.f : exp2f(S[nt][1]);
                p2 = (j0     > row0 + 8) ? 0.f : exp2f(S[nt][2]);
                p3 = (j0 + 1 > row0 + 8) ? 0.f : exp2f(S[nt][3]);
            }
            lacc0 += p0 + p1;  lacc1 += p2 + p3;
            __half b0 = __float2half_rn(p0), b1 = __float2half_rn(p1);
            __half b2 = __float2half_rn(p2), b3 = __float2half_rn(p3);
            int kg = nt >> 1, sl = (nt & 1) * 2;
            ph[kg][sl  ] = pk_us(__half_as_ushort(b0), __half_as_ushort(b1));
            ph[kg][sl+1] = pk_us(__half_as_ushort(b2), __half_as_ushort(b3));
            pl[kg][sl  ] = pk_us(
                __half_as_ushort(__float2half_rn(p0 - __half2float(b0))),
                __half_as_ushort(__float2half_rn(p1 - __half2float(b1))));
            pl[kg][sl+1] = pk_us(
                __half_as_ushort(__float2half_rn(p2 - __half2float(b2))),
                __half_as_ushort(__float2half_rn(p3 - __half2float(b3))));
        }

        // ---- PV: this warp's 32 keys x ALL 128 d; 2 terms (Ph,Pl) x V ----
        #pragma unroll
        for (int kg = 0; kg < 2; kg++) {
            int vr = s * 32 + kg * 16 + vrow;
            #pragma unroll
            for (int dq = 0; dq < 4; dq++) {
                uint32_t vh[2][4];
                #pragma unroll
                for (int u = 0; u < 2; u++) {
                    uint32_t vo = swz_l(vr, (dq * 2 + u) * 16 + vc8);
                    LDSM4T(vh[u][0],vh[u][1],vh[u][2],vh[u][3], sb + VTI + vo);
                }
                #pragma unroll
                for (int u = 0; u < 2; u++) {
                    MMA(O[2*(dq*2+u)  ], ph[kg][0],ph[kg][1],ph[kg][2],ph[kg][3], vh[u][0],vh[u][1]);
                    MMA(O[2*(dq*2+u)+1], ph[kg][0],ph[kg][1],ph[kg][2],ph[kg][3], vh[u][2],vh[u][3]);
                }
                #pragma unroll
                for (int u = 0; u < 2; u++) {
                    MMA(O[2*(dq*2+u)  ], pl[kg][0],pl[kg][1],pl[kg][2],pl[kg][3], vh[u][0],vh[u][1]);
                    MMA(O[2*(dq*2+u)+1], pl[kg][0],pl[kg][1],pl[kg][2],pl[kg][3], vh[u][2],vh[u][3]);
                }
            }
        }

        // ---- rotate tiles: wait staging, barrier, convert, barrier ----
        if (pf) {
            cp_wait0();
            __syncthreads();          // all reads of current tiles done
            #pragma unroll
            for (int it = 0; it < 4; it++) {
                int idx = tid + it * NT;
                int key = idx >> 5, d = (idx & 31) * 4;
                uint32_t o = swz_w(key, d);
                *(uint2*)(smc + KTI + o) = cvt4h(*(const float4*)(smc + STGK + (size_t)idx * 16));
                *(uint2*)(smc + VTI + o) = cvt4h(*(const float4*)(smc + STGV + (size_t)idx * 16));
            }
            __syncthreads();          // publish new tiles
        }
    }

    // ---- epilogue: reduce l (quad), combine O + l across s halves ----
    lacc0 += __shfl_xor_sync(0xffffffffu, lacc0, 1);
    lacc0 += __shfl_xor_sync(0xffffffffu, lacc0, 2);
    lacc1 += __shfl_xor_sync(0xffffffffu, lacc1, 1);
    lacc1 += __shfl_xor_sync(0xffffffffu, lacc1, 2);

    float* ored = (float*)(smc + STGK);   // staging 64KB: [128 rows][128 d] fp32
    float* lred = (float*)smc;            // Q region dead at epilogue
    __syncthreads();                      // all warps past mainloop

    if (s == 1) {
        if ((l & 3) == 0) { lred[row0] = lacc0; lred[row0 + 8] = lacc1; }
        #pragma unroll
        for (int nt = 0; nt < 16; nt++) {
            int d = nt * 8 + colb;
            *(float2*)(ored + (size_t)row0 * 128 + d)       = make_float2(O[nt][0], O[nt][1]);
            *(float2*)(ored + (size_t)(row0 + 8) * 128 + d) = make_float2(O[nt][2], O[nt][3]);
        }
    }
    __syncthreads();
    if (s == 0) {
        const float inv0 = 1.f / (lacc0 + lred[row0]);
        const float inv1 = 1.f / (lacc1 + lred[row0 + 8]);
        float* o0 = gout + ((size_t)(b * Sc + row0    ) * HD) + h * Dc;
        float* o1 = gout + ((size_t)(b * Sc + row0 + 8) * HD) + h * Dc;
        #pragma unroll
        for (int nt = 0; nt < 16; nt++) {
            int d = nt * 8 + colb;
            float2 a0 = *(const float2*)(ored + (size_t)row0 * 128 + d);
            float2 a1 = *(const float2*)(ored + (size_t)(row0 + 8) * 128 + d);
            *(float2*)(o0 + d) = make_float2((O[nt][0] + a0.x) * inv0, (O[nt][1] + a0.y) * inv0);
            *(float2*)(o1 + d) = make_float2((O[nt][2] + a1.x) * inv1, (O[nt][3] + a1.y) * inv1);
        }
    }
}

extern "C" void kernel_launch(void* const* d_in, const int* in_sizes, int n_in,
                              void* d_out, int out_size)
{
    const float* q  = (const float*)d_in[0];
    const float* k  = (const float*)d_in[1];
    const float* v  = (const float*)d_in[2];
    const float* kc = (const float*)d_in[3];
    const float* vc = (const float*)d_in[4];
    const int*  pos = (const int*)d_in[5];
    float* out = (float*)d_out;

    cudaFuncSetAttribute(sdpa_h16_kernel,
                         cudaFuncAttributeMaxDynamicSharedMemorySize, SMEM_BYTES);
    sdpa_h16_kernel<<<Bc * Hc, NT, SMEM_BYTES>>>(q, k, v, kc, vc, pos, out);
}

// round 16
// speedup vs baseline: 1.8508x; 1.3340x over previous
#include <cuda_runtime.h>
#include <cuda_fp16.h>
#include <cstdint>

constexpr int Bc = 4, Sc = 128, Hc = 32, Dc = 128, Tc = 2048;
constexpr int HD  = Hc * Dc;          // 4096
constexpr int KVB = 64;
constexpr int NT  = 512;              // threads

// smem layout (bytes)
constexpr uint32_t QTI  = 0;          // 128x128 fp16 = 32KB (epilogue: lred at smc+0)
constexpr uint32_t KTI  = 32768;      // 64x128 fp16 = 16KB
constexpr uint32_t VTI  = 49152;      // 16KB
constexpr uint32_t STGK = 65536;      // 64x128 fp32 = 32KB (epilogue: ored 64KB = STGK+STGV)
constexpr uint32_t STGV = 98304;
constexpr uint32_t SMEM_BYTES = 131072;   // 128KB

__device__ __forceinline__ uint32_t swz_w(int r, int d0) {   // 8B store addr (256B rows)
    return (uint32_t)(r * 256 + ((((d0 >> 3)) ^ (r & 7)) << 4) + ((d0 & 7) << 1));
}
__device__ __forceinline__ uint32_t swz_l(int r, int c0) {   // ldmatrix row addr (256B rows)
    return (uint32_t)(r * 256 + ((((c0 >> 3)) ^ (r & 7)) << 4));
}
__device__ __forceinline__ uint32_t smem_u32(const void* p) {
    uint32_t r;
    asm("{\n\t.reg .u64 t;\n\tcvta.to.shared.u64 t, %1;\n\tcvt.u32.u64 %0, t;\n\t}"
        : "=r"(r) : "l"(p));
    return r;
}

#define LDSM4(R0,R1,R2,R3,A) \
    asm volatile("ldmatrix.sync.aligned.m8n8.x4.shared.b16 {%0,%1,%2,%3}, [%4];" \
        : "=r"(R0),"=r"(R1),"=r"(R2),"=r"(R3) : "r"(A))
#define LDSM4T(R0,R1,R2,R3,A) \
    asm volatile("ldmatrix.sync.aligned.m8n8.x4.trans.shared.b16 {%0,%1,%2,%3}, [%4];" \
        : "=r"(R0),"=r"(R1),"=r"(R2),"=r"(R3) : "r"(A))
#define MMA(C,A0,A1,A2,A3,B0,B1) \
    asm volatile("mma.sync.aligned.m16n8k16.row.col.f32.f16.f16.f32 " \
        "{%0,%1,%2,%3}, {%4,%5,%6,%7}, {%8,%9}, {%0,%1,%2,%3};" \
        : "+f"((C)[0]),"+f"((C)[1]),"+f"((C)[2]),"+f"((C)[3]) \
        : "r"(A0),"r"(A1),"r"(A2),"r"(A3),"r"(B0),"r"(B1))

__device__ __forceinline__ void cp16(uint32_t dst, const void* src) {
    asm volatile("cp.async.cg.shared.global [%0], [%1], 16;"
                 :: "r"(dst), "l"(src) : "memory");
}
__device__ __forceinline__ void cp_commit() { asm volatile("cp.async.commit_group;" ::: "memory"); }
__device__ __forceinline__ void cp_wait0()  { asm volatile("cp.async.wait_group 0;" ::: "memory"); }

__device__ __forceinline__ uint32_t pk_us(unsigned short a, unsigned short b) {
    return (uint32_t)a | ((uint32_t)b << 16);
}
// single-precision fp16 convert
__device__ __forceinline__ uint2 cvt4h(float4 v) {
    return make_uint2(
        pk_us(__half_as_ushort(__float2half_rn(v.x)), __half_as_ushort(__float2half_rn(v.y))),
        pk_us(__half_as_ushort(__float2half_rn(v.z)), __half_as_ushort(__float2half_rn(v.w))));
}

__global__ void __launch_bounds__(NT, 1)
sdpa_h16s_kernel(const float* __restrict__ gq, const float* __restrict__ gk,
                 const float* __restrict__ gv, const float* __restrict__ gkc,
                 const float* __restrict__ gvc, const int* __restrict__ gpos,
                 float* __restrict__ gout)
{
    extern __shared__ char smc[];
    const uint32_t sb = smem_u32(smc);
    const int tid = threadIdx.x;
    const int wid = tid >> 5;
    const int l   = tid & 31;
    const int qt  = wid & 7;          // query tile (16 rows)
    const int s   = wid >> 3;         // key half (32 keys)
    const int bh = blockIdx.x, b = bh >> 5, h = bh & 31;

    const int start = *gpos;
    const int nkv   = start + Sc;
    const int nblk  = (nkv + KVB - 1) / KVB;

    const float* qb  = gq  + ((size_t)(b * Sc) * Hc + h) * Dc;
    const float* kcb = gkc + ((size_t)(b * Tc) * Hc + h) * Dc;
    const float* vcb = gvc + ((size_t)(b * Tc) * Hc + h) * Dc;
    const float* knb = gk  + ((size_t)(b * Sc) * Hc + h) * Dc;
    const float* vnb = gv  + ((size_t)(b * Sc) * Hc + h) * Dc;

    // ---- stage block 0 (K + V fp32) ----
    #pragma unroll
    for (int it = 0; it < 4; it++) {
        int idx = tid + it * NT;
        int key = idx >> 5, d = (idx & 31) * 4;
        const float* ks = (key < start) ? kcb + (size_t)key * HD + d
                                        : knb + (size_t)(key - start) * HD + d;
        const float* vs = (key < start) ? vcb + (size_t)key * HD + d
                                        : vnb + (size_t)(key - start) * HD + d;
        cp16(sb + STGK + (uint32_t)idx * 16, ks);
        cp16(sb + STGV + (uint32_t)idx * 16, vs);
    }
    cp_commit();

    // ---- prologue: Q -> smem fp16 (single), scale*log2(e) folded ----
    const float SCALE = 0.08838834764831845f * 1.4426950408889634f;
    #pragma unroll
    for (int it = 0; it < 8; it++) {
        int idx = tid + it * NT;
        int r = idx >> 5, d = (idx & 31) * 4;
        float4 qv = *(const float4*)(qb + (size_t)r * HD + d);
        qv.x *= SCALE; qv.y *= SCALE; qv.z *= SCALE; qv.w *= SCALE;
        *(uint2*)(smc + QTI + swz_w(r, d)) = cvt4h(qv);
    }

    float O[16][4];
    #pragma unroll
    for (int t = 0; t < 16; t++) { O[t][0]=O[t][1]=O[t][2]=O[t][3]=0.f; }
    float lacc0 = 0.f, lacc1 = 0.f;

    // fragment address constants
    const int q0   = qt * 16;
    const int row0 = q0 + (l >> 2);
    const int qrow = q0 + (l & 15);
    const int qc8  = (l >> 4) << 3;
    const int krow = (l & 7) + ((l >> 4) << 3);
    const int kc8  = ((l >> 3) & 1) << 3;
    const int vrow = (l & 7) + (((l >> 3) & 1) << 3);
    const int vc8  = (l >> 4) << 3;
    const int colb = (l & 3) * 2;

    // ---- convert block 0 staging -> fp16 tiles ----
    cp_wait0();
    #pragma unroll
    for (int it = 0; it < 4; it++) {
        int idx = tid + it * NT;
        int key = idx >> 5, d = (idx & 31) * 4;
        uint32_t o = swz_w(key, d);
        *(uint2*)(smc + KTI + o) = cvt4h(*(const float4*)(smc + STGK + (size_t)idx * 16));
        *(uint2*)(smc + VTI + o) = cvt4h(*(const float4*)(smc + STGV + (size_t)idx * 16));
    }
    __syncthreads();   // publish Q + tiles

    for (int blk = 0; blk < nblk; blk++) {
        const int t0 = blk * KVB;
        const bool pf = (blk + 1) < nblk;

        // ---- cp.async next block into staging (background) ----
        if (pf) {
            const int t0n = t0 + KVB;
            #pragma unroll
            for (int it = 0; it < 4; it++) {
                int idx = tid + it * NT;
                int key = idx >> 5, d = (idx & 31) * 4;
                int jg  = t0n + key;
                const float* ks = (jg < start) ? kcb + (size_t)jg * HD + d
                                               : knb + (size_t)(jg - start) * HD + d;
                const float* vs = (jg < start) ? vcb + (size_t)jg * HD + d
                                               : vnb + (size_t)(jg - start) * HD + d;
                cp16(sb + STGK + (uint32_t)idx * 16, ks);
                cp16(sb + STGV + (uint32_t)idx * 16, vs);
            }
            cp_commit();
        }

        // ---- QK^T: this warp's 32-key half; single term ----
        float S[4][4];
        #pragma unroll
        for (int t = 0; t < 4; t++) { S[t][0]=S[t][1]=S[t][2]=S[t][3]=0.f; }

        #pragma unroll
        for (int ks = 0; ks < 8; ks++) {
            int c0k = ks * 16 + kc8;
            uint32_t qh0,qh1,qh2,qh3;
            LDSM4(qh0,qh1,qh2,qh3, sb + QTI + swz_l(qrow, ks * 16 + qc8));
            uint32_t khf[2][4];
            #pragma unroll
            for (int np = 0; np < 2; np++) {
                uint32_t ko = swz_l(s * 32 + np * 16 + krow, c0k);
                LDSM4(khf[np][0],khf[np][1],khf[np][2],khf[np][3], sb + KTI + ko);
            }
            #pragma unroll
            for (int np = 0; np < 2; np++) {
                MMA(S[2*np  ], qh0,qh1,qh2,qh3, khf[np][0],khf[np][1]);
                MMA(S[2*np+1], qh0,qh1,qh2,qh3, khf[np][2],khf[np][3]);
            }
        }

        // ---- softmax + P pack to fp16 A-fragments (single) ----
        uint32_t ph[2][4];
        const bool needMask = (t0 + s * 32 + 31 - start) > q0;
        #pragma unroll
        for (int nt = 0; nt < 4; nt++) {
            float p0, p1, p2, p3;
            if (!needMask) {
                p0 = exp2f(S[nt][0]); p1 = exp2f(S[nt][1]);
                p2 = exp2f(S[nt][2]); p3 = exp2f(S[nt][3]);
            } else {
                int j0 = t0 + s * 32 + nt * 8 + colb - start;
                p0 = (j0     > row0    ) ? 0.f : exp2f(S[nt][0]);
                p1 = (j0 + 1 > row0    ) ? 0.f : exp2f(S[nt][1]);
                p2 = (j0     > row0 + 8) ? 0.f : exp2f(S[nt][2]);
                p3 = (j0 + 1 > row0 + 8) ? 0.f : exp2f(S[nt][3]);
            }
            lacc0 += p0 + p1;  lacc1 += p2 + p3;
            int kg = nt >> 1, sl = (nt & 1) * 2;
            ph[kg][sl  ] = pk_us(__half_as_ushort(__float2half_rn(p0)),
                                 __half_as_ushort(__float2half_rn(p1)));
            ph[kg][sl+1] = pk_us(__half_as_ushort(__float2half_rn(p2)),
                                 __half_as_ushort(__float2half_rn(p3)));
        }

        // ---- PV: this warp's 32 keys x ALL 128 d; single term ----
        #pragma unroll
        for (int kg = 0; kg < 2; kg++) {
            int vr = s * 32 + kg * 16 + vrow;
            #pragma unroll
            for (int dq = 0; dq < 4; dq++) {
                uint32_t vh[2][4];
                #pragma unroll
                for (int u = 0; u < 2; u++) {
                    uint32_t vo = swz_l(vr, (dq * 2 + u) * 16 + vc8);
                    LDSM4T(vh[u][0],vh[u][1],vh[u][2],vh[u][3], sb + VTI + vo);
                }
                #pragma unroll
                for (int u = 0; u < 2; u++) {
                    MMA(O[2*(dq*2+u)  ], ph[kg][0],ph[kg][1],ph[kg][2],ph[kg][3], vh[u][0],vh[u][1]);
                    MMA(O[2*(dq*2+u)+1], ph[kg][0],ph[kg][1],ph[kg][2],ph[kg][3], vh[u][2],vh[u][3]);
                }
            }
        }

        // ---- rotate tiles: wait staging, barrier, convert, barrier ----
        if (pf) {
            cp_wait0();
            __syncthreads();          // all reads of current tiles done
            #pragma unroll
            for (int it = 0; it < 4; it++) {
                int idx = tid + it * NT;
                int key = idx >> 5, d = (idx & 31) * 4;
                uint32_t o = swz_w(key, d);
                *(uint2*)(smc + KTI + o) = cvt4h(*(const float4*)(smc + STGK + (size_t)idx * 16));
                *(uint2*)(smc + VTI + o) = cvt4h(*(const float4*)(smc + STGV + (size_t)idx * 16));
            }
            __syncthreads();          // publish new tiles
        }
    }

    // ---- epilogue: reduce l (quad), combine O + l across s halves ----
    lacc0 += __shfl_xor_sync(0xffffffffu, lacc0, 1);
    lacc0 += __shfl_xor_sync(0xffffffffu, lacc0, 2);
    lacc1 += __shfl_xor_sync(0xffffffffu, lacc1, 1);
    lacc1 += __shfl_xor_sync(0xffffffffu, lacc1, 2);

    float* ored = (float*)(smc + STGK);   // staging 64KB: [128 rows][128 d] fp32
    float* lred = (float*)smc;            // Q region dead at epilogue
    __syncthreads();                      // all warps past mainloop

    if (s == 1) {
        if ((l & 3) == 0) { lred[row0] = lacc0; lred[row0 + 8] = lacc1; }
        #pragma unroll
        for (int nt = 0; nt < 16; nt++) {
            int d = nt * 8 + colb;
            *(float2*)(ored + (size_t)row0 * 128 + d)       = make_float2(O[nt][0], O[nt][1]);
            *(float2*)(ored + (size_t)(row0 + 8) * 128 + d) = make_float2(O[nt][2], O[nt][3]);
        }
    }
    __syncthreads();
    if (s == 0) {
        const float inv0 = 1.f / (lacc0 + lred[row0]);
        const float inv1 = 1.f / (lacc1 + lred[row0 + 8]);
        float* o0 = gout + ((size_t)(b * Sc + row0    ) * HD) + h * Dc;
        float* o1 = gout + ((size_t)(b * Sc + row0 + 8) * HD) + h * Dc;
        #pragma unroll
        for (int nt = 0; nt < 16; nt++) {
            int d = nt * 8 + colb;
            float2 a0 = *(const float2*)(ored + (size_t)row0 * 128 + d);
            float2 a1 = *(const float2*)(ored + (size_t)(row0 + 8) * 128 + d);
            *(float2*)(o0 + d) = make_float2((O[nt][0] + a0.x) * inv0, (O[nt][1] + a0.y) * inv0);
            *(float2*)(o1 + d) = make_float2((O[nt][2] + a1.x) * inv1, (O[nt][3] + a1.y) * inv1);
        }
    }
}

extern "C" void kernel_launch(void* const* d_in, const int* in_sizes, int n_in,
                              void* d_out, int out_size)
{
    const float* q  = (const float*)d_in[0];
    const float* k  = (const float*)d_in[1];
    const float* v  = (const float*)d_in[2];
    const float* kc = (const float*)d_in[3];
    const float* vc = (const float*)d_in[4];
    const int*  pos = (const int*)d_in[5];
    float* out = (float*)d_out;

    cudaFuncSetAttribute(sdpa_h16s_kernel,
                         cudaFuncAttributeMaxDynamicSharedMemorySize, SMEM_BYTES);
    sdpa_h16s_kernel<<<Bc * Hc, NT, SMEM_BYTES>>>(q, k, v, kc, vc, pos, out);
}